// round 12
// baseline (speedup 1.0000x reference)
#include <cuda_runtime.h>
#include <math.h>

// DifferentiableRGBtoVel: per-pixel softmax over 256 colormap colors.
//
// w_k = exp(-|p-c_k|^2/T), out = sum(w_k v_k)/sum(w_k), T = 0.01.
// Log2 domain, K = 100*log2(e): s_k = 2K p.c_k - K|c_k|^2 - K|p|^2.
// Per-pixel guaranteed shift t (16^3 LUT over the color cube) bounds the max
// shifted score in [-1, ~15.6] so packed fp16 ex2 is overflow/underflow safe:
// ONE ex2.approx.f16x2 per color pair.
//
// f16 -> f32 back-conversion without conversion instructions:
//   as_float((h & 0x7FFF) << 13) == value(h) * 2^-112  (exact, normal+subnormal)
// The uniform 2^-112 cancels in the softmax ratio.
//
// R11 model closure: dur = issue_wall * wave_factor. This round cuts both:
//  - coefficient loads 5 -> 3 per color-pair (float4+float4+float2 packing),
//    moved from __constant__ (LDC port floor 8) to __ldg globals (floor 4);
//    no memcpyToSymbol node.
//  - regs target 42 (launch_bounds(256,6)) for 48 warps/SM: wave 1.384->1.153.
//    sLUT smem stage deleted (LUT read via __ldg; L1-resident 16KB).

typedef unsigned long long ull;

#define NPAIR 128
#define PPT 4
#define THREADS 256
#define K_LOG2 144.26950408889634f       // 100 * log2(e)
#define NCELL 16
#define LUTSZ (NCELL * NCELL * NCELL)    // 4096
#define CELL_R 0.0541265877f             // sqrt(3)/32 half-diagonal
#define SHIFT_BIAS (-1.0f)

// Packed coefficients (written by precompute kernel, read via __ldg):
// g_XY[j] = { 2SK*cx(2j), 2SK*cx(2j+1), 2SK*cy(2j), 2SK*cy(2j+1) }
// g_ZH[j] = { 2SK*cz(2j), 2SK*cz(2j+1), -K|c(2j)|^2, -K|c(2j+1)|^2 }
// g_V [j] = { v(2j), v(2j+1) }
__device__ float4 g_XY[NPAIR];
__device__ float4 g_ZH[NPAIR];
__device__ float2 g_V[NPAIR];
__device__ float  g_lut[LUTSZ];  // per-cell shift t = K*(d_c + r)^2 + BIAS

// ---------------- packed f32x2 helpers ----------------
__device__ __forceinline__ ull pk2(float lo, float hi) {
    ull r; asm("mov.b64 %0, {%1, %2};" : "=l"(r) : "f"(lo), "f"(hi)); return r;
}
__device__ __forceinline__ void upk2(ull v, float& lo, float& hi) {
    asm("mov.b64 {%0, %1}, %2;" : "=f"(lo), "=f"(hi) : "l"(v));
}
__device__ __forceinline__ ull add2(ull a, ull b) {
    ull r; asm("add.rn.f32x2 %0, %1, %2;" : "=l"(r) : "l"(a), "l"(b)); return r;
}
__device__ __forceinline__ ull fma2(ull a, ull b, ull c) {
    ull r; asm("fma.rn.f32x2 %0, %1, %2, %3;" : "=l"(r) : "l"(a), "l"(b), "l"(c)); return r;
}

// scores (f32 pair) -> f16x2 -> ex2.f16x2 -> weights*2^-112 as f32 pair
__device__ __forceinline__ ull exp2w_pair(ull acc) {
    float lo, hi;
    upk2(acc, lo, hi);
    unsigned h2;
    asm("{\n\t.reg .b32 t;\n\t"
        "cvt.rn.f16x2.f32 t, %1, %2;\n\t"   // first src -> HIGH half
        "ex2.approx.f16x2 %0, t;\n\t}"
        : "=r"(h2) : "f"(hi), "f"(lo));
    unsigned lo32 = (h2 << 13) & 0x0FFFE000u;   // low half  -> f32 bits * 2^-112
    unsigned hi32 = (h2 >> 3)  & 0x0FFFE000u;   // high half -> f32 bits * 2^-112
    return pk2(__int_as_float(lo32), __int_as_float(hi32));
}

// ---------------- fused precompute: LUT + coefficients ----------------
__global__ void rgb2vel_pre(const float* __restrict__ cmap,
                            const float* __restrict__ v_i) {
    __shared__ float sc[768];
    int tid = threadIdx.x;
    for (int i = tid; i < 768; i += blockDim.x) sc[i] = cmap[i];
    __syncthreads();

    int cell = blockIdx.x * blockDim.x + tid;
    if (cell < LUTSZ) {
        int iz = cell & (NCELL - 1);
        int iy = (cell >> 4) & (NCELL - 1);
        int ix = cell >> 8;
        float cx = (ix + 0.5f) / NCELL;
        float cy = (iy + 0.5f) / NCELL;
        float cz = (iz + 0.5f) / NCELL;
        float best = 1e30f;
        for (int k = 0; k < 256; k++) {
            float dx = cx - sc[k*3+0];
            float dy = cy - sc[k*3+1];
            float dz = cz - sc[k*3+2];
            best = fminf(best, dx*dx + dy*dy + dz*dz);
        }
        float m = sqrtf(best) + CELL_R;  // >= d_min for any pixel in this cell
        g_lut[cell] = K_LOG2 * m * m + SHIFT_BIAS;
    }

    if (blockIdx.x == 0 && tid < NPAIR) {
        const float SK = sqrtf(K_LOG2);
        int j = tid, k0 = 2 * j, k1 = 2 * j + 1;
        float c0x = sc[k0*3+0], c0y = sc[k0*3+1], c0z = sc[k0*3+2];
        float c1x = sc[k1*3+0], c1y = sc[k1*3+1], c1z = sc[k1*3+2];
        g_XY[j] = make_float4(2.f*SK*c0x, 2.f*SK*c1x, 2.f*SK*c0y, 2.f*SK*c1y);
        g_ZH[j] = make_float4(2.f*SK*c0z, 2.f*SK*c1z,
                              -K_LOG2*(c0x*c0x + c0y*c0y + c0z*c0z),
                              -K_LOG2*(c1x*c1x + c1y*c1y + c1z*c1z));
        g_V[j]  = make_float2(v_i[k0], v_i[k1]);
    }
}

// ---------------- main kernel ----------------
__global__ void __launch_bounds__(THREADS, 6)
rgb2vel_main(const float* __restrict__ img, float* __restrict__ out,
             int plane, int total) {
    int t = threadIdx.x;
    int g = (blockIdx.x * THREADS + t) * PPT;
    if (g >= total) return;

    int n = g / plane;
    int r = g - n * plane;
    const float* base = img + (size_t)n * 3 * plane + r;
    float4 pr = *(const float4*)(base);
    float4 pg = *(const float4*)(base + plane);
    float4 pb = *(const float4*)(base + 2 * plane);

    const float SK = sqrtf(K_LOG2);
    float rv[PPT] = {pr.x, pr.y, pr.z, pr.w};
    float gv[PPT] = {pg.x, pg.y, pg.z, pg.w};
    float bv[PPT] = {pb.x, pb.y, pb.z, pb.w};

    ull tpx[PPT], tpy[PPT], tpz[PPT], np2[PPT], sumw[PPT], sumv[PPT];
#pragma unroll
    for (int p = 0; p < PPT; p++) {
        int ix = min((int)(rv[p] * NCELL), NCELL - 1);
        int iy = min((int)(gv[p] * NCELL), NCELL - 1);
        int iz = min((int)(bv[p] * NCELL), NCELL - 1);
        float shift = __ldg(&g_lut[(ix << 8) + (iy << 4) + iz]);
        float x = SK * rv[p], y = SK * gv[p], z = SK * bv[p];
        float s = shift - (x*x + y*y + z*z);      // t - K|p|^2
        tpx[p] = pk2(x, x);
        tpy[p] = pk2(y, y);
        tpz[p] = pk2(z, z);
        np2[p] = pk2(s, s);
        sumw[p] = 0ull;
        sumv[p] = 0ull;
    }

#pragma unroll 2
    for (int j = 0; j < NPAIR; j++) {
        float4 xy = __ldg(&g_XY[j]);
        float4 zh = __ldg(&g_ZH[j]);
        float2 v  = __ldg(&g_V[j]);
        ull xj = pk2(xy.x, xy.y);
        ull yj = pk2(xy.z, xy.w);
        ull zj = pk2(zh.x, zh.y);
        ull hj = pk2(zh.z, zh.w);
        ull vj = pk2(v.x, v.y);
#pragma unroll
        for (int p = 0; p < PPT; p++) {
            ull acc = add2(hj, np2[p]);         // -K|c|^2 + t - K|p|^2
            acc = fma2(tpx[p], xj, acc);        // + 2K p.x c.x
            acc = fma2(tpy[p], yj, acc);
            acc = fma2(tpz[p], zj, acc);        // shifted score pair (<= ~15.6)
            ull w2 = exp2w_pair(acc);           // weights * 2^-112 (exact bits)
            sumw[p] = add2(sumw[p], w2);
            sumv[p] = fma2(w2, vj, sumv[p]);
        }
    }

    float res[PPT];
#pragma unroll
    for (int p = 0; p < PPT; p++) {
        float wl, wh, vl, vh;
        upk2(sumw[p], wl, wh);
        upk2(sumv[p], vl, vh);
        res[p] = (vl + vh) / (wl + wh);         // shift and 2^-112 both cancel
    }
    *(float4*)(out + g) = make_float4(res[0], res[1], res[2], res[3]);
}

// ---------------- launch ----------------
extern "C" void kernel_launch(void* const* d_in, const int* in_sizes, int n_in,
                              void* d_out, int out_size) {
    const float* img = nullptr;
    const float* cmap = nullptr;
    const float* vi = nullptr;
    for (int i = 0; i < n_in; i++) {
        if (in_sizes[i] == 768)       cmap = (const float*)d_in[i];
        else if (in_sizes[i] == 256)  vi   = (const float*)d_in[i];
        else                          img  = (const float*)d_in[i];
    }
    float* out = (float*)d_out;

    int total = out_size;            // N*H*W pixels
    int plane = total / 4;           // H*W per image (N=4)

    rgb2vel_pre<<<LUTSZ / THREADS, THREADS>>>(cmap, vi);

    int threads_total = total / PPT;
    int blocks = (threads_total + THREADS - 1) / THREADS;
    rgb2vel_main<<<blocks, THREADS>>>(img, out, plane, total);
}

// round 13
// speedup vs baseline: 2.8038x; 2.8038x over previous
#include <cuda_runtime.h>
#include <math.h>

// DifferentiableRGBtoVel: per-pixel softmax over 256 colormap colors.
//
// w_k = exp(-|p-c_k|^2/T), out = sum(w_k v_k)/sum(w_k), T = 0.01.
// Log2 domain, K = 100*log2(e): s_k = 2K p.c_k - K|c_k|^2 - K|p|^2.
// Per-pixel guaranteed shift t (16^3 LUT over the color cube) bounds the max
// shifted score in [-1, ~15.6] so packed fp16 ex2 is overflow/underflow safe:
// ONE ex2.approx.f16x2 per color pair.
//
// f16 -> f32 back-conversion without conversion instructions:
//   as_float((h & 0x7FFF) << 13) == value(h) * 2^-112  (exact, normal+subnormal)
// The uniform 2^-112 cancels in the softmax ratio.
//
// R12 lesson: warp-uniform per-iteration coefficient reloads must use the
// constant/uniform path (LDCU) -- __ldg turned them into an L1tex wavefront
// storm (72.7us -> 235us). Constant bank restored here.
// This round: coefficient loads 5 -> 3 per color-pair (float4/float4/float2
// repack -> LDC.128 x2 + LDC.64), and launch_bounds(256,6) targeting <=42
// regs for 48 warps/SM (wave factor 1.384 -> 1.153). Unroll 1 to keep
// temporary pressure down (loop overhead cancels against load savings).

typedef unsigned long long ull;

#define NPAIR 128
#define PPT 4
#define THREADS 256
#define K_LOG2 144.26950408889634f       // 100 * log2(e)
#define NCELL 16
#define LUTSZ (NCELL * NCELL * NCELL)    // 4096
#define CELL_R 0.0541265877f             // sqrt(3)/32 half-diagonal
#define SHIFT_BIAS (-1.0f)

// Packed coefficients:
// XY[j] = { 2SK*cx(2j), 2SK*cx(2j+1), 2SK*cy(2j), 2SK*cy(2j+1) }
// ZH[j] = { 2SK*cz(2j), 2SK*cz(2j+1), -K|c(2j)|^2, -K|c(2j+1)|^2 }
// V [j] = { v(2j), v(2j+1) }
struct Coef {
    float4 XY[NPAIR];
    float4 ZH[NPAIR];
    float2 V[NPAIR];
};
__device__ Coef g_stage;       // written by precompute kernel
__constant__ Coef cC;          // copied from g_stage (D2D, capturable)
__device__ float g_lut[LUTSZ]; // per-cell shift t = K*(d_c + r)^2 + BIAS

// ---------------- packed f32x2 helpers ----------------
__device__ __forceinline__ ull pk2(float lo, float hi) {
    ull r; asm("mov.b64 %0, {%1, %2};" : "=l"(r) : "f"(lo), "f"(hi)); return r;
}
__device__ __forceinline__ void upk2(ull v, float& lo, float& hi) {
    asm("mov.b64 {%0, %1}, %2;" : "=f"(lo), "=f"(hi) : "l"(v));
}
__device__ __forceinline__ ull add2(ull a, ull b) {
    ull r; asm("add.rn.f32x2 %0, %1, %2;" : "=l"(r) : "l"(a), "l"(b)); return r;
}
__device__ __forceinline__ ull fma2(ull a, ull b, ull c) {
    ull r; asm("fma.rn.f32x2 %0, %1, %2, %3;" : "=l"(r) : "l"(a), "l"(b), "l"(c)); return r;
}

// scores (f32 pair) -> f16x2 -> ex2.f16x2 -> weights*2^-112 as f32 pair
__device__ __forceinline__ ull exp2w_pair(ull acc) {
    float lo, hi;
    upk2(acc, lo, hi);
    unsigned h2;
    asm("{\n\t.reg .b32 t;\n\t"
        "cvt.rn.f16x2.f32 t, %1, %2;\n\t"   // first src -> HIGH half
        "ex2.approx.f16x2 %0, t;\n\t}"
        : "=r"(h2) : "f"(hi), "f"(lo));
    unsigned lo32 = (h2 << 13) & 0x0FFFE000u;   // low half  -> f32 bits * 2^-112
    unsigned hi32 = (h2 >> 3)  & 0x0FFFE000u;   // high half -> f32 bits * 2^-112
    return pk2(__int_as_float(lo32), __int_as_float(hi32));
}

// ---------------- fused precompute: LUT + coefficients ----------------
__global__ void rgb2vel_pre(const float* __restrict__ cmap,
                            const float* __restrict__ v_i) {
    __shared__ float sc[768];
    int tid = threadIdx.x;
    for (int i = tid; i < 768; i += blockDim.x) sc[i] = cmap[i];
    __syncthreads();

    int cell = blockIdx.x * blockDim.x + tid;
    if (cell < LUTSZ) {
        int iz = cell & (NCELL - 1);
        int iy = (cell >> 4) & (NCELL - 1);
        int ix = cell >> 8;
        float cx = (ix + 0.5f) / NCELL;
        float cy = (iy + 0.5f) / NCELL;
        float cz = (iz + 0.5f) / NCELL;
        float best = 1e30f;
        for (int k = 0; k < 256; k++) {
            float dx = cx - sc[k*3+0];
            float dy = cy - sc[k*3+1];
            float dz = cz - sc[k*3+2];
            best = fminf(best, dx*dx + dy*dy + dz*dz);
        }
        float m = sqrtf(best) + CELL_R;  // >= d_min for any pixel in this cell
        g_lut[cell] = K_LOG2 * m * m + SHIFT_BIAS;
    }

    if (blockIdx.x == 0 && tid < NPAIR) {
        const float SK = sqrtf(K_LOG2);
        int j = tid, k0 = 2 * j, k1 = 2 * j + 1;
        float c0x = sc[k0*3+0], c0y = sc[k0*3+1], c0z = sc[k0*3+2];
        float c1x = sc[k1*3+0], c1y = sc[k1*3+1], c1z = sc[k1*3+2];
        g_stage.XY[j] = make_float4(2.f*SK*c0x, 2.f*SK*c1x, 2.f*SK*c0y, 2.f*SK*c1y);
        g_stage.ZH[j] = make_float4(2.f*SK*c0z, 2.f*SK*c1z,
                                    -K_LOG2*(c0x*c0x + c0y*c0y + c0z*c0z),
                                    -K_LOG2*(c1x*c1x + c1y*c1y + c1z*c1z));
        g_stage.V[j]  = make_float2(v_i[k0], v_i[k1]);
    }
}

// ---------------- main kernel ----------------
__global__ void __launch_bounds__(THREADS, 6)
rgb2vel_main(const float* __restrict__ img, float* __restrict__ out,
             int plane, int total) {
    int t = threadIdx.x;
    int g = (blockIdx.x * THREADS + t) * PPT;
    if (g >= total) return;

    int n = g / plane;
    int r = g - n * plane;
    const float* base = img + (size_t)n * 3 * plane + r;
    float4 pr = *(const float4*)(base);
    float4 pg = *(const float4*)(base + plane);
    float4 pb = *(const float4*)(base + 2 * plane);

    const float SK = sqrtf(K_LOG2);
    float rv[PPT] = {pr.x, pr.y, pr.z, pr.w};
    float gv[PPT] = {pg.x, pg.y, pg.z, pg.w};
    float bv[PPT] = {pb.x, pb.y, pb.z, pb.w};

    ull tpx[PPT], tpy[PPT], tpz[PPT], np2[PPT], sumw[PPT], sumv[PPT];
#pragma unroll
    for (int p = 0; p < PPT; p++) {
        int ix = min((int)(rv[p] * NCELL), NCELL - 1);
        int iy = min((int)(gv[p] * NCELL), NCELL - 1);
        int iz = min((int)(bv[p] * NCELL), NCELL - 1);
        float shift = g_lut[(ix << 8) + (iy << 4) + iz];
        float x = SK * rv[p], y = SK * gv[p], z = SK * bv[p];
        float s = shift - (x*x + y*y + z*z);      // t - K|p|^2
        tpx[p] = pk2(x, x);
        tpy[p] = pk2(y, y);
        tpz[p] = pk2(z, z);
        np2[p] = pk2(s, s);
        sumw[p] = 0ull;
        sumv[p] = 0ull;
    }

    // warp-uniform constant-bank reads -> LDCU / uniform-register path
    const ulonglong2* cXY = (const ulonglong2*)cC.XY;
    const ulonglong2* cZH = (const ulonglong2*)cC.ZH;
    const ull*        cV  = (const ull*)cC.V;

#pragma unroll 1
    for (int j = 0; j < NPAIR; j++) {
        ulonglong2 xy = cXY[j];      // {X pair, Y pair}
        ulonglong2 zh = cZH[j];      // {Z pair, H pair}
        ull vj = cV[j];
        ull xj = xy.x, yj = xy.y, zj = zh.x, hj = zh.y;
#pragma unroll
        for (int p = 0; p < PPT; p++) {
            ull acc = add2(hj, np2[p]);         // -K|c|^2 + t - K|p|^2
            acc = fma2(tpx[p], xj, acc);        // + 2K p.x c.x
            acc = fma2(tpy[p], yj, acc);
            acc = fma2(tpz[p], zj, acc);        // shifted score pair (<= ~15.6)
            ull w2 = exp2w_pair(acc);           // weights * 2^-112 (exact bits)
            sumw[p] = add2(sumw[p], w2);
            sumv[p] = fma2(w2, vj, sumv[p]);
        }
    }

    float res[PPT];
#pragma unroll
    for (int p = 0; p < PPT; p++) {
        float wl, wh, vl, vh;
        upk2(sumw[p], wl, wh);
        upk2(sumv[p], vl, vh);
        res[p] = (vl + vh) / (wl + wh);         // shift and 2^-112 both cancel
    }
    *(float4*)(out + g) = make_float4(res[0], res[1], res[2], res[3]);
}

// ---------------- launch ----------------
extern "C" void kernel_launch(void* const* d_in, const int* in_sizes, int n_in,
                              void* d_out, int out_size) {
    const float* img = nullptr;
    const float* cmap = nullptr;
    const float* vi = nullptr;
    for (int i = 0; i < n_in; i++) {
        if (in_sizes[i] == 768)       cmap = (const float*)d_in[i];
        else if (in_sizes[i] == 256)  vi   = (const float*)d_in[i];
        else                          img  = (const float*)d_in[i];
    }
    float* out = (float*)d_out;

    int total = out_size;            // N*H*W pixels
    int plane = total / 4;           // H*W per image (N=4)

    rgb2vel_pre<<<LUTSZ / THREADS, THREADS>>>(cmap, vi);

    void* stage_ptr = nullptr;
    cudaGetSymbolAddress(&stage_ptr, g_stage);
    cudaMemcpyToSymbolAsync(cC, stage_ptr, sizeof(Coef), 0,
                            cudaMemcpyDeviceToDevice, 0);

    int threads_total = total / PPT;
    int blocks = (threads_total + THREADS - 1) / THREADS;
    rgb2vel_main<<<blocks, THREADS>>>(img, out, plane, total);
}